// round 1
// baseline (speedup 1.0000x reference)
#include <cuda_runtime.h>

// ---------------------------------------------------------------------------
// EvalNet: EmbeddingBag(sum,pad) -> screlu -> fc2(1024->32) -> screlu
//          -> bucketed cp/wdl heads.
// K1: column-chunked gather with the 64-col table slice staged in SMEM
//     (conflict-free LDS.128 gather), writes screlu'd h to global scratch.
// K2: register-tiled fp32 "GEMM" h[B,1024] x fc2_w^T[1024,32] + heads.
// ---------------------------------------------------------------------------

#define HIDDEN   1024
#define NROWS    769          // INPUT_DIM + 1 (row 768 = padding row, zeros)
#define CHUNK    64           // columns per K1 block (769*64*4 = 196864 B smem)
#define NCHUNKS  (HIDDEN / CHUNK)   // 16
#define NGROUPS  9            // 16*9 = 144 blocks ~= 148 SMs, 1 CTA/SM
#define K1T      512
#define TILE     32           // samples per K1 inner tile (16 thr/sample)
#define MAX_B    16384

#define K2T      256
#define TS       128          // samples per K2 block
#define CK       64           // c-chunk for K2 staging

__device__ float g_h[(size_t)MAX_B * HIDDEN];   // screlu'd hidden, fp32
__device__ int   g_is64;                        // index dtype flag

// ---------------------------------------------------------------------------
// K0: detect whether x / piece_count are int64 or int32.
// Values are in [0,768], so if int64 every odd 32-bit word is 0.
// Probability of that under int32 uniform [0,768] over 1000+ words is ~0.
// ---------------------------------------------------------------------------
__global__ void detect_kernel(const unsigned int* __restrict__ w, int n_elems)
{
    __shared__ int nz;
    if (threadIdx.x == 0) nz = 0;
    __syncthreads();
    int limit = n_elems < 2048 ? n_elems : 2048;  // safe under int32 sizing
    int found = 0;
    for (int i = 2 * threadIdx.x + 1; i < limit; i += 2 * blockDim.x)
        if (w[i] != 0u) found = 1;
    if (found) atomicOr(&nz, 1);
    __syncthreads();
    if (threadIdx.x == 0) g_is64 = (nz == 0) ? 1 : 0;
}

__device__ __forceinline__ float screlu1(float v)
{
    float c = fminf(fmaxf(v, 0.0f), 1.0f);
    return c * c;
}

// ---------------------------------------------------------------------------
// K1: gather + bias + screlu for a 64-column slice.
// grid = (NCHUNKS, NGROUPS); block = 512.
// Thread (s = tid/16, q = tid%16) accumulates float4 cols [q*4, q*4+4)
// for sample s of the current 32-sample tile.
// Gather is LDS.128: per phase 8 lanes read 128B contiguous -> conflict-free.
// ---------------------------------------------------------------------------
__global__ __launch_bounds__(K1T)
void gather_kernel(const void* __restrict__ xv,
                   const float* __restrict__ emb,
                   const float* __restrict__ bias1,
                   int B)
{
    extern __shared__ char smem[];
    float* s_tab  = (float*)smem;                                   // NROWS*CHUNK
    int*   s_idx  = (int*)(smem + NROWS * CHUNK * 4);               // TILE*32
    float* s_bias = (float*)(smem + NROWS * CHUNK * 4 + TILE * 32 * 4); // CHUNK

    const int tid   = threadIdx.x;
    const int chunk = blockIdx.x;
    const int cbase = chunk * CHUNK;
    const int is64  = g_is64;

    // Stage the table slice: 769 rows x 64 cols (float4 granularity).
    const float4* embv = (const float4*)emb;
    float4*       tabv = (float4*)s_tab;
    for (int i = tid; i < NROWS * (CHUNK / 4); i += K1T) {
        int row = i / (CHUNK / 4);
        int c4  = i % (CHUNK / 4);
        tabv[i] = embv[row * (HIDDEN / 4) + (cbase / 4) + c4];
    }
    if (tid < CHUNK) s_bias[tid] = bias1[cbase + tid];

    const int s = tid >> 4;     // 0..31 : sample within tile
    const int q = tid & 15;     // 0..15 : float4 column group

    const int spg     = (B + NGROUPS - 1) / NGROUPS;
    const int s_begin = blockIdx.y * spg;
    const int s_end   = min(B, s_begin + spg);

    const int*       x32 = (const int*)xv;
    const long long* x64 = (const long long*)xv;

    for (int t0 = s_begin; t0 < s_end; t0 += TILE) {
        __syncthreads();   // also orders table staging before first gather
        // Stage indices for this tile (1024 ints, coalesced).
        for (int i = tid; i < TILE * 32; i += K1T) {
            int samp = t0 + (i >> 5);
            int v = NROWS - 1;                 // pad row (zeros) if OOB
            if (samp < B) {
                int r = i & 31;
                v = is64 ? (int)x64[(size_t)samp * 32 + r]
                         : x32[samp * 32 + r];
            }
            s_idx[i] = v;
        }
        __syncthreads();

        int samp = t0 + s;
        if (samp < B) {
            float4 acc = make_float4(0.f, 0.f, 0.f, 0.f);
            #pragma unroll
            for (int r0 = 0; r0 < 32; r0 += 8) {
                int id[8];
                #pragma unroll
                for (int k = 0; k < 8; k++) id[k] = s_idx[s * 32 + r0 + k];
                #pragma unroll
                for (int k = 0; k < 8; k++) {
                    float4 v = tabv[id[k] * (CHUNK / 4) + q];
                    acc.x += v.x; acc.y += v.y; acc.z += v.z; acc.w += v.w;
                }
            }
            float4 b = ((const float4*)s_bias)[q];
            acc.x = screlu1(acc.x + b.x);
            acc.y = screlu1(acc.y + b.y);
            acc.z = screlu1(acc.z + b.z);
            acc.w = screlu1(acc.w + b.w);
            ((float4*)(g_h + (size_t)samp * HIDDEN + cbase))[q] = acc;
        }
    }
}

// ---------------------------------------------------------------------------
// K2: h2 = screlu(h @ fc2_w^T + fc2_b), then bucketed cp/wdl heads.
// Block: 128 samples, 256 threads; each thread owns a 4x4 (sample x j) tile.
// h staged per 64-c chunk with padded stride (bank-conflict-free);
// fc2_w staged transposed with stride 33.
// ---------------------------------------------------------------------------
__global__ __launch_bounds__(K2T)
void fc_kernel(const float* __restrict__ fc2_w, const float* __restrict__ fc2_b,
               const float* __restrict__ cp_w,  const float* __restrict__ cp_b,
               const float* __restrict__ wdl_w, const float* __restrict__ wdl_b,
               const void* __restrict__ pcv, float* __restrict__ out, int B)
{
    __shared__ float h_tile[TS][CK + 4];       // stride 68 (16B aligned rows)
    __shared__ float wt[CK * 33];              // wt[c*33 + j]
    __shared__ float s_cp_w[8 * 32];
    __shared__ float s_wdl_w[24 * 32];
    __shared__ float s_cp_b[8];
    __shared__ float s_wdl_b[24];
    __shared__ float s_fc2_b[32];

    const int tid = threadIdx.x;
    const int s0  = blockIdx.x * TS;
    const int is64 = g_is64;

    // Stage head weights once.
    if (tid < 256) s_cp_w[tid] = cp_w[tid];
    for (int i = tid; i < 24 * 32; i += K2T) s_wdl_w[i] = wdl_w[i];
    if (tid < 8)  s_cp_b[tid]  = cp_b[tid];
    if (tid < 24) s_wdl_b[tid] = wdl_b[tid];
    if (tid < 32) s_fc2_b[tid] = fc2_b[tid];

    const int jq = tid & 7;     // 8 j-groups of 4
    const int sg = tid >> 3;    // 32 sample-groups of 4

    float acc[4][4];
    #pragma unroll
    for (int i = 0; i < 4; i++)
        #pragma unroll
        for (int j = 0; j < 4; j++) acc[i][j] = 0.f;

    for (int c0 = 0; c0 < HIDDEN; c0 += CK) {
        __syncthreads();
        // Stage fc2_w transposed: wt[c*33 + j] = fc2_w[j][c0+c].
        for (int i = tid; i < CK * 32; i += K2T) {
            int c = i % CK, j = i / CK;
            wt[c * 33 + j] = fc2_w[j * HIDDEN + c0 + c];
        }
        // Stage h tile (coalesced float4 loads).
        for (int i = tid; i < TS * (CK / 4); i += K2T) {
            int sl = i / (CK / 4), c4 = i % (CK / 4);
            float4 v = ((const float4*)(g_h + (size_t)(s0 + sl) * HIDDEN + c0))[c4];
            *(float4*)&h_tile[sl][c4 * 4] = v;
        }
        __syncthreads();

        #pragma unroll 4
        for (int c = 0; c < CK; c++) {
            float hv[4], wv[4];
            #pragma unroll
            for (int i = 0; i < 4; i++) hv[i] = h_tile[sg * 4 + i][c];
            #pragma unroll
            for (int j = 0; j < 4; j++) wv[j] = wt[c * 33 + jq * 4 + j];
            #pragma unroll
            for (int i = 0; i < 4; i++)
                #pragma unroll
                for (int j = 0; j < 4; j++)
                    acc[i][j] = fmaf(hv[i], wv[j], acc[i][j]);
        }
    }

    // Reuse h_tile storage for h2 (34.8KB >= 128*33*4 = 16.9KB).
    float* s_h2 = &h_tile[0][0];   // index: s*33 + j
    __syncthreads();
    #pragma unroll
    for (int i = 0; i < 4; i++) {
        #pragma unroll
        for (int j = 0; j < 4; j++) {
            int jj = jq * 4 + j;
            float v = screlu1(acc[i][j] + s_fc2_b[jj]);
            s_h2[(sg * 4 + i) * 33 + jj] = v;
        }
    }
    __syncthreads();

    // Heads: one thread per sample.
    if (tid < TS) {
        int samp = s0 + tid;
        if (samp < B) {
            int pc = is64 ? (int)((const long long*)pcv)[samp]
                          : ((const int*)pcv)[samp];
            int bkt = (pc - 2) * 8 / 30;          // matches jax floordiv after clamp
            bkt = max(0, min(7, bkt));

            const float* h2 = &s_h2[tid * 33];
            float cp = s_cp_b[bkt];
            float w0 = s_wdl_b[bkt * 3 + 0];
            float w1 = s_wdl_b[bkt * 3 + 1];
            float w2 = s_wdl_b[bkt * 3 + 2];
            const float* cw  = &s_cp_w[bkt * 32];
            const float* ww0 = &s_wdl_w[(bkt * 3 + 0) * 32];
            const float* ww1 = &s_wdl_w[(bkt * 3 + 1) * 32];
            const float* ww2 = &s_wdl_w[(bkt * 3 + 2) * 32];
            #pragma unroll
            for (int j = 0; j < 32; j++) {
                float hh = h2[j];
                cp = fmaf(hh, cw[j],  cp);
                w0 = fmaf(hh, ww0[j], w0);
                w1 = fmaf(hh, ww1[j], w1);
                w2 = fmaf(hh, ww2[j], w2);
            }
            out[samp] = cp;                        // cp block  [0, B)
            out[B + samp * 3 + 0] = w0;            // wdl block [B, 4B)
            out[B + samp * 3 + 1] = w1;
            out[B + samp * 3 + 2] = w2;
        }
    }
}

// ---------------------------------------------------------------------------
extern "C" void kernel_launch(void* const* d_in, const int* in_sizes, int n_in,
                              void* d_out, int out_size)
{
    const void*  x      = d_in[0];
    const void*  pc     = d_in[1];
    const float* emb    = (const float*)d_in[2];
    const float* bias1  = (const float*)d_in[3];
    const float* fc2_w  = (const float*)d_in[4];
    const float* fc2_b  = (const float*)d_in[5];
    const float* cp_w   = (const float*)d_in[6];
    const float* cp_b   = (const float*)d_in[7];
    const float* wdl_w  = (const float*)d_in[8];
    const float* wdl_b  = (const float*)d_in[9];

    int B = in_sizes[0] / 32;
    if (B > MAX_B) B = MAX_B;   // scratch bound (setup fixes B=16384)

    detect_kernel<<<1, 256>>>((const unsigned int*)x, in_sizes[0]);

    const int k1_smem = NROWS * CHUNK * 4 + TILE * 32 * 4 + CHUNK * 4; // 201216 B
    cudaFuncSetAttribute(gather_kernel,
                         cudaFuncAttributeMaxDynamicSharedMemorySize, k1_smem);
    dim3 g1(NCHUNKS, NGROUPS);
    gather_kernel<<<g1, K1T, k1_smem>>>(x, emb, bias1, B);

    int g2 = (B + TS - 1) / TS;
    fc_kernel<<<g2, K2T>>>(fc2_w, fc2_b, cp_w, cp_b, wdl_w, wdl_b,
                           pc, (float*)d_out, B);
}